// round 15
// baseline (speedup 1.0000x reference)
#include <cuda_runtime.h>
#include <cuda_fp16.h>
#include <cstdint>

// ---------------------------------------------------------------------------
// Scratch buffers (static __device__ globals — no allocation allowed).
// Activations live here as channel-pair-interleaved half2 (viewed as u32).
// ---------------------------------------------------------------------------
__device__ float g_bufA[33554432];
__device__ float g_bufB[67108864];
__device__ float g_bufC[33554432];
__device__ float g_wt[262144];          // prepacked half2 weights (u32 view)

// ---------------------------------------------------------------------------
// Helpers
// ---------------------------------------------------------------------------
__device__ __forceinline__ uint32_t packh2(float lo, float hi)
{
    __half2 h = __floats2half2_rn(lo, hi);   // .x = lo = low 16 bits
    return *reinterpret_cast<uint32_t*>(&h);
}

__device__ __forceinline__ float unpackh(uint32_t u, int parity)
{
    __half2 h = *reinterpret_cast<__half2*>(&u);
    return __half2float(parity ? __high2half(h) : __low2half(h));
}

__device__ __forceinline__ void mma_f16(float* c,
                                        uint32_t a0, uint32_t a1,
                                        uint32_t a2, uint32_t a3,
                                        uint32_t b0, uint32_t b1)
{
    asm volatile(
        "mma.sync.aligned.m16n8k16.row.col.f32.f16.f16.f32 "
        "{%0,%1,%2,%3}, {%4,%5,%6,%7}, {%8,%9}, {%0,%1,%2,%3};\n"
        : "+f"(c[0]), "+f"(c[1]), "+f"(c[2]), "+f"(c[3])
        : "r"(a0), "r"(a1), "r"(a2), "r"(a3), "r"(b0), "r"(b1));
}

__device__ __forceinline__ uint32_t smem_u32(const void* p)
{
    return (uint32_t)__cvta_generic_to_shared(p);
}

// 16B cp.async; src-size 0 -> 16 zero bytes written (halo padding).
__device__ __forceinline__ void cp16z(uint32_t dst, const void* src, bool ok)
{
    int sz = ok ? 16 : 0;
    asm volatile("cp.async.ca.shared.global [%0], [%1], 16, %2;"
                 :: "r"(dst), "l"(src), "r"(sz));
}

// ---------------------------------------------------------------------------
// Implicit-GEMM 3x3 conv (pad=1), fp16 mma.sync.m16n8k16, f32 accumulate.
// Activations channel-pair-interleaved half2 (one u32 per pixel per cpair).
//
// Pipeline (NEW): ALL weights staged into smem ONCE up front (they are
// chunk-loop invariant); the chunk loop stages tiles only, depth-1 ahead,
// into an NB-buffer ring (NB=2 for NCH<=2, NB=3 for NCH=4), with exactly
// ONE __syncthreads per chunk (ring safety: stage(ch+1) issued in iter ch
// after sync(ch-1) which guarantees compute(ch-2) done; (ch+1)%3==(ch-2)%3).
//
// K order: k = r*16 + cipair*2 + parity (r = dy*3+dx). Each k16 step = one
// kernel tap r; B fragments are single u32 LDS with compile-time offsets.
// Weight smem layout per chunk [cb2(NCB)][ks][gid(8)][tig(4)][q(4)]: the
// full A fragment is ONE LDS.128 (conflict-free); staging is affine 16B.
// Output tile: NCB*16 couts x (TH h x 32 w), 256 thr.
//   TH=8 (stride-1): warp = one row; M=MM co-tiles/warp, B frags reused.
//   TH=4 (stride-2): warp = (co half, row); M=1, NCB=2.
// CHEP ≡ 8 (mod 32) -> stride-1 B loads conflict-free.
// ---------------------------------------------------------------------------
template<int STRIDE, int CIN, int BR, int TH, int MM, int OCC>
__global__ __launch_bounds__(256, OCC)
void conv3x3_h(const uint32_t* __restrict__ in, const uint32_t* __restrict__ w,
               const float* __restrict__ bias, uint32_t* __restrict__ out,
               int Cout, int Hin, int Win)
{
    constexpr int TW = 32;
    constexpr int M    = (TH == 8) ? MM : 1;
    constexpr int NCB  = (TH == 8) ? MM : 2;            // co-tiles per block
    constexpr int TIH  = TH * STRIDE + 2;               // 10 / 10
    constexpr int TIWP = (TW * STRIDE + 5 + 3) & ~3;    // 40 / 72 (pixels=u32)
    constexpr int RU   = TIWP / 4;                      // 16B units per row
    constexpr int PL   = TIH * RU;                      // units per cp plane
    constexpr int CHE  = TIH * TIWP;
    constexpr int CHEP = ((CHE + 8 + 31) & ~31) | 8;    // ≡8 mod 32 (424/744)
    constexpr int TILE_N = 8 * CHEP;                    // u32 per tile buffer
    constexpr int NCH  = CIN / 16;                      // 16 ci per chunk
    constexpr int NB   = (NCH <= 2) ? 2 : 3;            // tile ring depth
    constexpr int WN   = NCB * 1152;                    // u32 per weight chunk
    constexpr int WALL = NCH * WN;                      // u32, all weights
    constexpr int TU   = 8 * PL;
    constexpr int TITER = (TU + 255) / 256;
    constexpr bool HOIST = (STRIDE == 1);

    extern __shared__ __align__(16) uint32_t smem[];    // [w_all | tiles NB]

    const int Hout = Hin / STRIDE, Wout = Win / STRIDE;
    const int tid = threadIdx.x;
    const int groups = Cout / (NCB * 16);
    const int g  = blockIdx.z % groups;
    const int b  = blockIdx.z / groups;
    const int bx = blockIdx.x, by = blockIdx.y;

    const int y0 = by * TH * STRIDE - 1;
    const int x0 = bx * TW * STRIDE - 4;    // 16B-aligned halo (logical -1 = col 3)
    const size_t HW = (size_t)Hin * Win;    // u32 per channel pair
    const uint32_t* ibase = in + (size_t)b * (CIN / 2) * HW;
    const uint32_t* wbase = w + (size_t)g * WALL;

    const uint32_t wbuf_s = smem_u32(smem);
    const uint32_t tile_s = smem_u32(smem + WALL);

    // --- hoisted tile-staging descriptors (stride-1 only) ---
    int      h_soff[TITER];     // signed 32-bit gmem offset from ibase
    uint32_t h_doff[TITER];     // smem byte offset within tile buffer
    bool     h_ok[TITER];
    if (HOIST) {
        #pragma unroll
        for (int it = 0; it < TITER; it++) {
            int u = tid + it * 256;
            int uc = (u < TU) ? u : 0;
            int cp8 = uc / PL;
            int rem = uc - cp8 * PL;
            int r = rem / RU, uu = rem - r * RU;
            int gy = y0 + r, gx = x0 + 4 * uu;
            h_ok[it]   = (gy >= 0) && (gy < Hin) && (gx >= 0) && (gx < Win);
            h_soff[it] = cp8 * (int)HW + gy * Win + gx;
            h_doff[it] = 4u * (uint32_t)(cp8 * CHEP + r * TIWP + 4 * uu);
        }
    }

    auto load_tile = [&](int ch, int bi) {
        const uint32_t* isrc = ibase + (size_t)(ch * 8) * HW;
        uint32_t td = tile_s + (uint32_t)bi * 4u * TILE_N;
        if (HOIST) {
            #pragma unroll
            for (int it = 0; it < TITER; it++)
                if (tid + it * 256 < TU)
                    cp16z(td + h_doff[it], isrc + h_soff[it], h_ok[it]);
        } else {
            #pragma unroll 4
            for (int u = tid; u < TU; u += 256) {
                int cp8 = u / PL;
                int rem = u - cp8 * PL;
                int r = rem / RU, uu = rem - r * RU;
                int gy = y0 + r, gx = x0 + 4 * uu;
                bool ok = (gy >= 0) && (gy < Hin) && (gx >= 0) && (gx < Win);
                cp16z(td + 4u * (uint32_t)(cp8 * CHEP + r * TIWP + 4 * uu),
                      isrc + (size_t)cp8 * HW + (size_t)gy * Win + gx, ok);
            }
        }
    };

    const int lane = tid & 31, wid = tid >> 5;
    const int tig = lane & 3, gid = lane >> 2;
    const int mh = (TH == 8) ? 0 : (wid & 1);
    const int nq = (TH == 8) ? wid : (wid >> 1);

    float acc[M][4][4];
    #pragma unroll
    for (int m = 0; m < M; m++) {
        const int cb = (TH == 8) ? m * 16 : mh * 16;
        float bv0 = 0.0f, bv1 = 0.0f;
        if (BR) {
            bv0 = bias[g * (NCB * 16) + cb + gid];
            bv1 = bias[g * (NCB * 16) + cb + gid + 8];
        }
        #pragma unroll
        for (int t = 0; t < 4; t++) {
            acc[m][t][0] = bv0; acc[m][t][1] = bv0;
            acc[m][t][2] = bv1; acc[m][t][3] = bv1;
        }
    }

    // Prologue: ALL weights (affine 16B copy) + tile 0, one commit group.
    #pragma unroll 4
    for (int u = tid; u < WALL / 4; u += 256)
        cp16z(wbuf_s + 16u * (uint32_t)u, wbase + 4 * u, true);
    load_tile(0, 0);
    asm volatile("cp.async.commit_group;");

    #pragma unroll
    for (int ch = 0; ch < NCH; ch++) {
        if (ch + 1 < NCH) {
            load_tile(ch + 1, (ch + 1) % NB);
            asm volatile("cp.async.commit_group;");
            asm volatile("cp.async.wait_group 1;");
        } else {
            asm volatile("cp.async.wait_group 0;");
        }
        __syncthreads();    // ONE barrier per chunk

        const uint32_t* st = smem + WALL + (ch % NB) * TILE_N;
        const uint32_t* sw = smem + ch * WN;
        // Register bases; all tap/pixel offsets are compile-time immediates.
        const uint32_t* bp1 = st + tig * CHEP + nq * STRIDE * TIWP + gid * STRIDE + 3;
        const uint32_t* bp2 = bp1 + 4 * CHEP;
        const uint32_t* apb = sw + ((TH == 8) ? 0 : mh * 1152) + 4 * lane;

        #pragma unroll
        for (int ks = 0; ks < 9; ks++) {
            const int KO = (ks / 3) * TIWP + (ks % 3);   // compile-time per ks
            uint4 va[M];
            #pragma unroll
            for (int m = 0; m < M; m++)
                va[m] = *reinterpret_cast<const uint4*>(apb + m * 1152 + ks * 128);
            #pragma unroll
            for (int t = 0; t < 4; t++) {
                uint32_t b0 = bp1[KO + t * 8 * STRIDE];
                uint32_t b1 = bp2[KO + t * 8 * STRIDE];
                #pragma unroll
                for (int m = 0; m < M; m++)
                    mma_f16(acc[m][t], va[m].x, va[m].y, va[m].z, va[m].w, b0, b1);
            }
        }
    }

    // Epilogue: pair up (even, odd) co via shfl_xor(4), store half2 (u32x2).
    const int hrow = by * TH + nq;
    const size_t HWo = (size_t)Hout * Wout;
    #pragma unroll
    for (int m = 0; m < M; m++) {
        const int cb = (TH == 8) ? m * 16 : mh * 16;
        const int cbg = g * (NCB * 16) + cb;
        #pragma unroll
        for (int t = 0; t < 4; t++) {
            float v0 = acc[m][t][0], v1 = acc[m][t][1];
            float v2 = acc[m][t][2], v3 = acc[m][t][3];
            if (BR) {
                v0 = fmaxf(v0, 0.0f); v1 = fmaxf(v1, 0.0f);
                v2 = fmaxf(v2, 0.0f); v3 = fmaxf(v3, 0.0f);
            }
            float p0 = __shfl_xor_sync(0xffffffffu, v0, 4);
            float p1 = __shfl_xor_sync(0xffffffffu, v1, 4);
            float p2 = __shfl_xor_sync(0xffffffffu, v2, 4);
            float p3 = __shfl_xor_sync(0xffffffffu, v3, 4);
            const int wg = bx * 32 + t * 8 + 2 * tig;
            uint2 st2;
            int copair;
            if ((gid & 1) == 0) {
                st2.x = packh2(v0, p0);
                st2.y = packh2(v1, p1);
                copair = (cbg + gid) >> 1;
            } else {
                st2.x = packh2(p2, v2);
                st2.y = packh2(p3, v3);
                copair = (cbg + gid + 7) >> 1;
            }
            *reinterpret_cast<uint2*>(
                out + ((size_t)b * (Cout / 2) + copair) * HWo
                    + (size_t)hrow * Wout + wg) = st2;
        }
    }
}

// ---------------------------------------------------------------------------
// ConvOffset2D bilinear sampling on interleaved-half2 buffers, TWO adjacent
// pixels (w even, w+1) per thread. The torch raw-reshape offset words for
// both pixels form one 16B-aligned uint4 (flat indices 2G..2G+3, same
// channel word — p0 even guarantees no channel crossing). Gathers for the
// pixel pair share cache lines; output is one uint2.
// ---------------------------------------------------------------------------
__global__ void deform_h2(const uint32_t* __restrict__ x,
                          const uint32_t* __restrict__ off,
                          uint32_t* __restrict__ out,
                          int wsh, int hsh, int csh, int total_out2)
{
    int idx = blockIdx.x * 256 + threadIdx.x;
    if (idx >= total_out2) return;
    const int W = 1 << wsh, H = 1 << hsh;
    const int sh2 = wsh + hsh;
    const unsigned HW = 1u << sh2;
    const int C = 1 << csh;

    int pp2 = idx & ((HW >> 1) - 1);
    int p0 = pp2 * 2;
    int cpair = (idx >> (sh2 - 1)) & ((1 << (csh - 1)) - 1);
    int b = idx >> (sh2 - 1 + csh - 1);
    int h = p0 >> wsh;
    int w0 = p0 & (W - 1);

    const uint32_t* xb = x + (size_t)b * (C / 2) * HW;
    const uint32_t* ob = off + (size_t)b * C * HW;

    float res[2][2];    // [px][par]
    #pragma unroll
    for (int par = 0; par < 2; par++) {
        int c = 2 * cpair + par;
        unsigned G0 = (unsigned)c * HW + (unsigned)p0;
        unsigned F0 = 2u * G0;
        unsigned co0 = F0 >> sh2;           // same for both pixels (p0 even)
        unsigned pq  = F0 & (HW - 1);       // multiple of 4 -> uint4 aligned
        uint4 ow4 = *reinterpret_cast<const uint4*>(
            ob + (size_t)(co0 >> 1) * HW + pq);
        const int parity = co0 & 1;
        const uint32_t* xp = xb + (size_t)cpair * HW;
        #pragma unroll
        for (int px = 0; px < 2; px++) {
            float o0 = unpackh(px ? ow4.z : ow4.x, parity);
            float o1 = unpackh(px ? ow4.w : ow4.y, parity);
            float r  = fminf(fmaxf(o0 + (float)h,         0.0f), (float)(H - 1));
            float cc = fminf(fmaxf(o1 + (float)(w0 + px), 0.0f), (float)(W - 1));
            float r0f = floorf(r), c0f = floorf(cc);
            int r0 = (int)r0f, r1 = (int)ceilf(r);
            int c0 = (int)c0f, c1 = (int)ceilf(cc);
            float vlt = unpackh(xp[(r0 << wsh) + c0], par);
            float vrb = unpackh(xp[(r1 << wsh) + c1], par);
            float vlb = unpackh(xp[(r0 << wsh) + c1], par);
            float vrt = unpackh(xp[(r1 << wsh) + c0], par);
            float fr = r - r0f, fc = cc - c0f;
            float vt = vlt + (vrt - vlt) * fr;
            float vb = vlb + (vrb - vlb) * fr;
            res[px][par] = vt + (vb - vt) * fc;
        }
    }
    *reinterpret_cast<uint2*>(out + (size_t)idx * 2) =
        make_uint2(packh2(res[0][0], res[0][1]), packh2(res[1][0], res[1][1]));
}

// ---------------------------------------------------------------------------
// Weight prepass (ONE launch): all 7 tensors -> half2, linear layout
// [g][ch(16ci)][cb2(NCB)][ks(9)][gid(8)][tig(4)][q(4)]:
//   co = g*(NCB*16) + cb2*16 + gid + (q&1)*8, cipair = tig + (q>>1)*4
//   half2 = (W[ci even], W[ci odd]) at tap ks, ci = ch*16 + cipair*2.
// ---------------------------------------------------------------------------
struct PrepDesc {
    const float* src[7];
    int cin[7];
    int ncb[7];
    int off[8];         // prefix sums in u32 elements
};

__global__ void prep_all_h(PrepDesc d, uint32_t* __restrict__ dst)
{
    int i = blockIdx.x * 256 + threadIdx.x;
    if (i >= d.off[7]) return;
    int s = 0;
    #pragma unroll
    for (int k = 0; k < 6; k++) s += (i >= d.off[k + 1]) ? 1 : 0;
    int j = i - d.off[s];
    const int CIN = d.cin[s];
    const int NCH = CIN >> 4;
    const int NCB = d.ncb[s];

    int q   = j & 3;
    int tig = (j >> 2) & 3;
    int gid = (j >> 4) & 7;
    int ks  = (j >> 7) % 9;
    int rest = j / 1152;
    int cb2 = rest % NCB; rest /= NCB;
    int ch  = rest % NCH;
    int gi  = rest / NCH;

    int co = gi * (NCB * 16) + cb2 * 16 + gid + (q & 1) * 8;
    int cipair = tig + (q >> 1) * 4;
    int ci = ch * 16 + cipair * 2;
    const float* sp = d.src[s] + (((size_t)co * CIN + ci) * 9 + ks);
    dst[i] = packh2(sp[0], sp[9]);
}

// ---------------------------------------------------------------------------
// x prepass: NCHW f32 -> interleaved half2 (vectorized 4 px/thread).
// ---------------------------------------------------------------------------
__global__ void cvt_x4(const float4* __restrict__ src, uint4* __restrict__ dst,
                       int sh2m2, int total4)
{
    int i = blockIdx.x * 256 + threadIdx.x;
    if (i >= total4) return;
    int poff = i & ((1 << sh2m2) - 1);
    int pair = i >> sh2m2;
    float4 a = src[(((size_t)pair * 2)     << sh2m2) + poff];
    float4 c = src[(((size_t)pair * 2 + 1) << sh2m2) + poff];
    dst[i] = make_uint4(packh2(a.x, c.x), packh2(a.y, c.y),
                        packh2(a.z, c.z), packh2(a.w, c.w));
}

// ---------------------------------------------------------------------------
// Global average pool from interleaved half2. One block per channel pair.
// ---------------------------------------------------------------------------
__global__ void avgpool_h(const uint32_t* __restrict__ in,
                          float* __restrict__ out, int HW, int halfC)
{
    const uint32_t* p = in + (size_t)blockIdx.x * HW;
    float lo = 0.0f, hi = 0.0f;
    for (int i = threadIdx.x; i < HW; i += 256) {
        float2 f = __half22float2(*reinterpret_cast<const __half2*>(p + i));
        lo += f.x; hi += f.y;
    }
    __shared__ float smlo[256], smhi[256];
    smlo[threadIdx.x] = lo; smhi[threadIdx.x] = hi;
    __syncthreads();
    for (int st = 128; st > 0; st >>= 1) {
        if (threadIdx.x < st) {
            smlo[threadIdx.x] += smlo[threadIdx.x + st];
            smhi[threadIdx.x] += smhi[threadIdx.x + st];
        }
        __syncthreads();
    }
    if (threadIdx.x == 0) {
        int b = blockIdx.x / halfC, cp = blockIdx.x % halfC;
        out[b * 2 * halfC + 2 * cp]     = smlo[0] / (float)HW;
        out[b * 2 * halfC + 2 * cp + 1] = smhi[0] / (float)HW;
    }
}

// ---------------------------------------------------------------------------
// Launch pipeline (graph-capturable: kernel launches + attribute sets only).
// ---------------------------------------------------------------------------
static inline int conv_smem_bytes(int stride, int th, int ncb, int cin)
{
    int tih  = th * stride + 2;
    int tiwp = (32 * stride + 5 + 3) & ~3;
    int che  = tih * tiwp;
    int chep = ((che + 8 + 31) & ~31) | 8;
    int tile_n = 8 * chep;
    int nch = cin / 16;
    int nb = (nch <= 2) ? 2 : 3;
    return (nch * ncb * 1152 + nb * tile_n) * 4;
}

extern "C" void kernel_launch(void* const* d_in, const int* in_sizes, int n_in,
                              void* d_out, int out_size)
{
    const float* x   = (const float*)d_in[0];
    const float* w1  = (const float*)d_in[1];
    const float* b1  = (const float*)d_in[2];
    const float* ow1 = (const float*)d_in[3];
    const float* w2  = (const float*)d_in[4];
    const float* b2  = (const float*)d_in[5];
    const float* ow2 = (const float*)d_in[6];
    const float* w3  = (const float*)d_in[7];
    const float* b3  = (const float*)d_in[8];
    const float* ow3 = (const float*)d_in[9];
    const float* w4  = (const float*)d_in[10];
    const float* b4  = (const float*)d_in[11];
    float* outp = (float*)d_out;

    float *Af, *Bf, *Cf, *WTf;
    cudaGetSymbolAddress((void**)&Af, g_bufA);
    cudaGetSymbolAddress((void**)&Bf, g_bufB);
    cudaGetSymbolAddress((void**)&Cf, g_bufC);
    cudaGetSymbolAddress((void**)&WTf, g_wt);
    uint32_t* A  = (uint32_t*)Af;
    uint32_t* B  = (uint32_t*)Bf;
    uint32_t* C  = (uint32_t*)Cf;
    uint32_t* WT = (uint32_t*)WTf;

    const int S_C1  = conv_smem_bytes(1, 8, 2, 32);   // conv1: 45568
    const int S_O1  = conv_smem_bytes(1, 8, 4, 32);   // offconv1/3: 64000
    const int S_O2  = conv_smem_bytes(1, 8, 4, 64);   // offconv2: 114432
    const int S_S2  = conv_smem_bytes(2, 4, 2, 32);   // conv2/conv4: 66048
    const int S_S2L = conv_smem_bytes(2, 4, 2, 64);   // conv3: 108288
    cudaFuncSetAttribute(conv3x3_h<1, 32, 1, 8, 2, 3>, cudaFuncAttributeMaxDynamicSharedMemorySize, S_C1);
    cudaFuncSetAttribute(conv3x3_h<1, 32, 0, 8, 4, 2>, cudaFuncAttributeMaxDynamicSharedMemorySize, S_O1);
    cudaFuncSetAttribute(conv3x3_h<1, 64, 0, 8, 4, 2>, cudaFuncAttributeMaxDynamicSharedMemorySize, S_O2);
    cudaFuncSetAttribute(conv3x3_h<2, 32, 1, 4, 1, 3>, cudaFuncAttributeMaxDynamicSharedMemorySize, S_S2);
    cudaFuncSetAttribute(conv3x3_h<2, 64, 1, 4, 1, 2>, cudaFuncAttributeMaxDynamicSharedMemorySize, S_S2L);

    // Prepacked weights (u32 offsets): w1 4608 | ow1 9216 | w2 9216 |
    // ow2 36864 | w3 9216 | ow3 9216 | w4 4608
    uint32_t* w1t  = WT;
    uint32_t* ow1t = WT + 4608;
    uint32_t* w2t  = WT + 13824;
    uint32_t* ow2t = WT + 23040;
    uint32_t* w3t  = WT + 59904;
    uint32_t* ow3t = WT + 69120;
    uint32_t* w4t  = WT + 78336;

    {
        PrepDesc d;
        d.src[0] = w1;  d.cin[0] = 32; d.ncb[0] = 2;
        d.src[1] = ow1; d.cin[1] = 32; d.ncb[1] = 4;
        d.src[2] = w2;  d.cin[2] = 32; d.ncb[2] = 2;
        d.src[3] = ow2; d.cin[3] = 64; d.ncb[3] = 4;
        d.src[4] = w3;  d.cin[4] = 64; d.ncb[4] = 2;
        d.src[5] = ow3; d.cin[5] = 32; d.ncb[5] = 4;
        d.src[6] = w4;  d.cin[6] = 32; d.ncb[6] = 2;
        d.off[0] = 0;     d.off[1] = 4608;  d.off[2] = 13824;
        d.off[3] = 23040; d.off[4] = 59904; d.off[5] = 69120;
        d.off[6] = 78336; d.off[7] = 82944;
        prep_all_h<<<(82944 + 255) / 256, 256>>>(d, WT);
    }
    {
        // x (16,32,256,256) f32 -> interleaved half2 in C
        int total4 = 16 * 16 * 65536 / 4;   // u32 count / 4
        cvt_x4<<<(total4 + 255) / 256, 256>>>((const float4*)x, (uint4*)C, 14, total4);
    }

    // 1) conv1: C(x~) -> A (16,32,256,256), bias+relu  [M=2, OCC=3]
    conv3x3_h<1, 32, 1, 8, 2, 3><<<dim3(8, 32, 16), 256, S_C1>>>(C, w1t, b1, A, 32, 256, 256);

    // 2) offconv1: A -> B (16,64,256,256)  [M=4, 64-cout blocks]
    conv3x3_h<1, 32, 0, 8, 4, 2><<<dim3(8, 32, 16), 256, S_O1>>>(A, ow1t, nullptr, B, 64, 256, 256);

    // 3) deform1: A,B -> C (16,32,256,256) ; 8.39M pixel-pairs
    deform_h2<<<32768, 256>>>(A, B, C, 8, 8, 5, 16 * 16 * 65536 / 2);

    // 4) conv2 stride2: C -> A (16,64,128,128), bias+relu
    conv3x3_h<2, 32, 1, 4, 1, 3><<<dim3(4, 32, 32), 256, S_S2>>>(C, w2t, b2, A, 64, 256, 256);

    // 5) offconv2: A -> B (16,128,128,128)  [M=4, NCH=4, 3-buffer ring]
    conv3x3_h<1, 64, 0, 8, 4, 2><<<dim3(4, 16, 32), 256, S_O2>>>(A, ow2t, nullptr, B, 128, 128, 128);

    // 6) deform2: A,B -> C (16,64,128,128) ; 4.19M pixel-pairs
    deform_h2<<<16384, 256>>>(A, B, C, 7, 7, 6, 16 * 32 * 16384 / 2);

    // 7) conv3 stride2: C -> A (16,32,64,64), bias+relu  [NCH=4 -> OCC=2]
    conv3x3_h<2, 64, 1, 4, 1, 2><<<dim3(2, 16, 16), 256, S_S2L>>>(C, w3t, b3, A, 32, 128, 128);

    // 8) offconv3: A -> B (16,64,64,64)  [M=4]
    conv3x3_h<1, 32, 0, 8, 4, 2><<<dim3(2, 8, 16), 256, S_O1>>>(A, ow3t, nullptr, B, 64, 64, 64);

    // 9) deform3: A,B -> C (16,32,64,64) ; 524288 pixel-pairs
    deform_h2<<<2048, 256>>>(A, B, C, 6, 6, 5, 16 * 16 * 4096 / 2);

    // 10) conv4 stride2: C -> A (16,32,32,32), bias+relu
    conv3x3_h<2, 32, 1, 4, 1, 3><<<dim3(1, 8, 16), 256, S_S2>>>(C, w4t, b4, A, 32, 64, 64);

    // 11) global avg pool: A (interleaved) -> out f32 (16,32,1,1)
    avgpool_h<<<256, 256>>>(A, outp, 1024, 16);
}

// round 16
// speedup vs baseline: 1.0030x; 1.0030x over previous
#include <cuda_runtime.h>
#include <cuda_fp16.h>
#include <cstdint>

// ---------------------------------------------------------------------------
// Scratch buffers (static __device__ globals — no allocation allowed).
// Activations live here as channel-pair-interleaved half2 (viewed as u32).
// ---------------------------------------------------------------------------
__device__ float g_bufA[33554432];
__device__ float g_bufB[67108864];
__device__ float g_bufC[33554432];
__device__ float g_wt[262144];          // prepacked half2 weights (u32 view)

// ---------------------------------------------------------------------------
// Helpers
// ---------------------------------------------------------------------------
__device__ __forceinline__ uint32_t packh2(float lo, float hi)
{
    __half2 h = __floats2half2_rn(lo, hi);   // .x = lo = low 16 bits
    return *reinterpret_cast<uint32_t*>(&h);
}

__device__ __forceinline__ float unpackh(uint32_t u, int parity)
{
    __half2 h = *reinterpret_cast<__half2*>(&u);
    return __half2float(parity ? __high2half(h) : __low2half(h));
}

__device__ __forceinline__ void mma_f16(float* c,
                                        uint32_t a0, uint32_t a1,
                                        uint32_t a2, uint32_t a3,
                                        uint32_t b0, uint32_t b1)
{
    asm volatile(
        "mma.sync.aligned.m16n8k16.row.col.f32.f16.f16.f32 "
        "{%0,%1,%2,%3}, {%4,%5,%6,%7}, {%8,%9}, {%0,%1,%2,%3};\n"
        : "+f"(c[0]), "+f"(c[1]), "+f"(c[2]), "+f"(c[3])
        : "r"(a0), "r"(a1), "r"(a2), "r"(a3), "r"(b0), "r"(b1));
}

__device__ __forceinline__ uint32_t smem_u32(const void* p)
{
    return (uint32_t)__cvta_generic_to_shared(p);
}

// 16B cp.async; src-size 0 -> 16 zero bytes written (halo padding).
__device__ __forceinline__ void cp16z(uint32_t dst, const void* src, bool ok)
{
    int sz = ok ? 16 : 0;
    asm volatile("cp.async.ca.shared.global [%0], [%1], 16, %2;"
                 :: "r"(dst), "l"(src), "r"(sz));
}

// ---------------------------------------------------------------------------
// Implicit-GEMM 3x3 conv (pad=1), fp16 mma.sync.m16n8k16, f32 accumulate.
// Activations channel-pair-interleaved half2 (one u32 per pixel per cpair).
//
// Pipeline (NEW): ALL weights staged into smem ONCE up front (they are
// chunk-loop invariant); the chunk loop stages tiles only, depth-1 ahead,
// into an NB-buffer ring (NB=2 for NCH<=2, NB=3 for NCH=4), with exactly
// ONE __syncthreads per chunk (ring safety: stage(ch+1) issued in iter ch
// after sync(ch-1) which guarantees compute(ch-2) done; (ch+1)%3==(ch-2)%3).
//
// K order: k = r*16 + cipair*2 + parity (r = dy*3+dx). Each k16 step = one
// kernel tap r; B fragments are single u32 LDS with compile-time offsets.
// Weight smem layout per chunk [cb2(NCB)][ks][gid(8)][tig(4)][q(4)]: the
// full A fragment is ONE LDS.128 (conflict-free); staging is affine 16B.
// Output tile: NCB*16 couts x (TH h x 32 w), 256 thr.
//   TH=8 (stride-1): warp = one row; M=MM co-tiles/warp, B frags reused.
//   TH=4 (stride-2): warp = (co half, row); M=1, NCB=2.
// CHEP ≡ 8 (mod 32) -> stride-1 B loads conflict-free.
// ---------------------------------------------------------------------------
template<int STRIDE, int CIN, int BR, int TH, int MM, int OCC>
__global__ __launch_bounds__(256, OCC)
void conv3x3_h(const uint32_t* __restrict__ in, const uint32_t* __restrict__ w,
               const float* __restrict__ bias, uint32_t* __restrict__ out,
               int Cout, int Hin, int Win)
{
    constexpr int TW = 32;
    constexpr int M    = (TH == 8) ? MM : 1;
    constexpr int NCB  = (TH == 8) ? MM : 2;            // co-tiles per block
    constexpr int TIH  = TH * STRIDE + 2;               // 10 / 10
    constexpr int TIWP = (TW * STRIDE + 5 + 3) & ~3;    // 40 / 72 (pixels=u32)
    constexpr int RU   = TIWP / 4;                      // 16B units per row
    constexpr int PL   = TIH * RU;                      // units per cp plane
    constexpr int CHE  = TIH * TIWP;
    constexpr int CHEP = ((CHE + 8 + 31) & ~31) | 8;    // ≡8 mod 32 (424/744)
    constexpr int TILE_N = 8 * CHEP;                    // u32 per tile buffer
    constexpr int NCH  = CIN / 16;                      // 16 ci per chunk
    constexpr int NB   = (NCH <= 2) ? 2 : 3;            // tile ring depth
    constexpr int WN   = NCB * 1152;                    // u32 per weight chunk
    constexpr int WALL = NCH * WN;                      // u32, all weights
    constexpr int TU   = 8 * PL;
    constexpr int TITER = (TU + 255) / 256;
    constexpr bool HOIST = (STRIDE == 1);

    extern __shared__ __align__(16) uint32_t smem[];    // [w_all | tiles NB]

    const int Hout = Hin / STRIDE, Wout = Win / STRIDE;
    const int tid = threadIdx.x;
    const int groups = Cout / (NCB * 16);
    const int g  = blockIdx.z % groups;
    const int b  = blockIdx.z / groups;
    const int bx = blockIdx.x, by = blockIdx.y;

    const int y0 = by * TH * STRIDE - 1;
    const int x0 = bx * TW * STRIDE - 4;    // 16B-aligned halo (logical -1 = col 3)
    const size_t HW = (size_t)Hin * Win;    // u32 per channel pair
    const uint32_t* ibase = in + (size_t)b * (CIN / 2) * HW;
    const uint32_t* wbase = w + (size_t)g * WALL;

    const uint32_t wbuf_s = smem_u32(smem);
    const uint32_t tile_s = smem_u32(smem + WALL);

    // --- hoisted tile-staging descriptors (stride-1 only) ---
    int      h_soff[TITER];     // signed 32-bit gmem offset from ibase
    uint32_t h_doff[TITER];     // smem byte offset within tile buffer
    bool     h_ok[TITER];
    if (HOIST) {
        #pragma unroll
        for (int it = 0; it < TITER; it++) {
            int u = tid + it * 256;
            int uc = (u < TU) ? u : 0;
            int cp8 = uc / PL;
            int rem = uc - cp8 * PL;
            int r = rem / RU, uu = rem - r * RU;
            int gy = y0 + r, gx = x0 + 4 * uu;
            h_ok[it]   = (gy >= 0) && (gy < Hin) && (gx >= 0) && (gx < Win);
            h_soff[it] = cp8 * (int)HW + gy * Win + gx;
            h_doff[it] = 4u * (uint32_t)(cp8 * CHEP + r * TIWP + 4 * uu);
        }
    }

    auto load_tile = [&](int ch, int bi) {
        const uint32_t* isrc = ibase + (size_t)(ch * 8) * HW;
        uint32_t td = tile_s + (uint32_t)bi * 4u * TILE_N;
        if (HOIST) {
            #pragma unroll
            for (int it = 0; it < TITER; it++)
                if (tid + it * 256 < TU)
                    cp16z(td + h_doff[it], isrc + h_soff[it], h_ok[it]);
        } else {
            #pragma unroll 4
            for (int u = tid; u < TU; u += 256) {
                int cp8 = u / PL;
                int rem = u - cp8 * PL;
                int r = rem / RU, uu = rem - r * RU;
                int gy = y0 + r, gx = x0 + 4 * uu;
                bool ok = (gy >= 0) && (gy < Hin) && (gx >= 0) && (gx < Win);
                cp16z(td + 4u * (uint32_t)(cp8 * CHEP + r * TIWP + 4 * uu),
                      isrc + (size_t)cp8 * HW + (size_t)gy * Win + gx, ok);
            }
        }
    };

    const int lane = tid & 31, wid = tid >> 5;
    const int tig = lane & 3, gid = lane >> 2;
    const int mh = (TH == 8) ? 0 : (wid & 1);
    const int nq = (TH == 8) ? wid : (wid >> 1);

    float acc[M][4][4];
    #pragma unroll
    for (int m = 0; m < M; m++) {
        const int cb = (TH == 8) ? m * 16 : mh * 16;
        float bv0 = 0.0f, bv1 = 0.0f;
        if (BR) {
            bv0 = bias[g * (NCB * 16) + cb + gid];
            bv1 = bias[g * (NCB * 16) + cb + gid + 8];
        }
        #pragma unroll
        for (int t = 0; t < 4; t++) {
            acc[m][t][0] = bv0; acc[m][t][1] = bv0;
            acc[m][t][2] = bv1; acc[m][t][3] = bv1;
        }
    }

    // Prologue: ALL weights (affine 16B copy) + tile 0, one commit group.
    #pragma unroll 4
    for (int u = tid; u < WALL / 4; u += 256)
        cp16z(wbuf_s + 16u * (uint32_t)u, wbase + 4 * u, true);
    load_tile(0, 0);
    asm volatile("cp.async.commit_group;");

    #pragma unroll
    for (int ch = 0; ch < NCH; ch++) {
        if (ch + 1 < NCH) {
            load_tile(ch + 1, (ch + 1) % NB);
            asm volatile("cp.async.commit_group;");
            asm volatile("cp.async.wait_group 1;");
        } else {
            asm volatile("cp.async.wait_group 0;");
        }
        __syncthreads();    // ONE barrier per chunk

        const uint32_t* st = smem + WALL + (ch % NB) * TILE_N;
        const uint32_t* sw = smem + ch * WN;
        // Register bases; all tap/pixel offsets are compile-time immediates.
        const uint32_t* bp1 = st + tig * CHEP + nq * STRIDE * TIWP + gid * STRIDE + 3;
        const uint32_t* bp2 = bp1 + 4 * CHEP;
        const uint32_t* apb = sw + ((TH == 8) ? 0 : mh * 1152) + 4 * lane;

        #pragma unroll
        for (int ks = 0; ks < 9; ks++) {
            const int KO = (ks / 3) * TIWP + (ks % 3);   // compile-time per ks
            uint4 va[M];
            #pragma unroll
            for (int m = 0; m < M; m++)
                va[m] = *reinterpret_cast<const uint4*>(apb + m * 1152 + ks * 128);
            #pragma unroll
            for (int t = 0; t < 4; t++) {
                uint32_t b0 = bp1[KO + t * 8 * STRIDE];
                uint32_t b1 = bp2[KO + t * 8 * STRIDE];
                #pragma unroll
                for (int m = 0; m < M; m++)
                    mma_f16(acc[m][t], va[m].x, va[m].y, va[m].z, va[m].w, b0, b1);
            }
        }
    }

    // Epilogue: pair up (even, odd) co via shfl_xor(4), store half2 (u32x2).
    const int hrow = by * TH + nq;
    const size_t HWo = (size_t)Hout * Wout;
    #pragma unroll
    for (int m = 0; m < M; m++) {
        const int cb = (TH == 8) ? m * 16 : mh * 16;
        const int cbg = g * (NCB * 16) + cb;
        #pragma unroll
        for (int t = 0; t < 4; t++) {
            float v0 = acc[m][t][0], v1 = acc[m][t][1];
            float v2 = acc[m][t][2], v3 = acc[m][t][3];
            if (BR) {
                v0 = fmaxf(v0, 0.0f); v1 = fmaxf(v1, 0.0f);
                v2 = fmaxf(v2, 0.0f); v3 = fmaxf(v3, 0.0f);
            }
            float p0 = __shfl_xor_sync(0xffffffffu, v0, 4);
            float p1 = __shfl_xor_sync(0xffffffffu, v1, 4);
            float p2 = __shfl_xor_sync(0xffffffffu, v2, 4);
            float p3 = __shfl_xor_sync(0xffffffffu, v3, 4);
            const int wg = bx * 32 + t * 8 + 2 * tig;
            uint2 st2;
            int copair;
            if ((gid & 1) == 0) {
                st2.x = packh2(v0, p0);
                st2.y = packh2(v1, p1);
                copair = (cbg + gid) >> 1;
            } else {
                st2.x = packh2(p2, v2);
                st2.y = packh2(p3, v3);
                copair = (cbg + gid + 7) >> 1;
            }
            *reinterpret_cast<uint2*>(
                out + ((size_t)b * (Cout / 2) + copair) * HWo
                    + (size_t)hrow * Wout + wg) = st2;
        }
    }
}

// ---------------------------------------------------------------------------
// ConvOffset2D bilinear sampling on interleaved-half2 buffers, TWO adjacent
// pixels (w even, w+1) per thread. The torch raw-reshape offset words for
// both pixels form one 16B-aligned uint4 (flat indices 2G..2G+3, same
// channel word — p0 even guarantees no channel crossing). Gathers for the
// pixel pair share cache lines; output is one uint2.
// ---------------------------------------------------------------------------
__global__ void deform_h2(const uint32_t* __restrict__ x,
                          const uint32_t* __restrict__ off,
                          uint32_t* __restrict__ out,
                          int wsh, int hsh, int csh, int total_out2)
{
    int idx = blockIdx.x * 256 + threadIdx.x;
    if (idx >= total_out2) return;
    const int W = 1 << wsh, H = 1 << hsh;
    const int sh2 = wsh + hsh;
    const unsigned HW = 1u << sh2;
    const int C = 1 << csh;

    int pp2 = idx & ((HW >> 1) - 1);
    int p0 = pp2 * 2;
    int cpair = (idx >> (sh2 - 1)) & ((1 << (csh - 1)) - 1);
    int b = idx >> (sh2 - 1 + csh - 1);
    int h = p0 >> wsh;
    int w0 = p0 & (W - 1);

    const uint32_t* xb = x + (size_t)b * (C / 2) * HW;
    const uint32_t* ob = off + (size_t)b * C * HW;

    float res[2][2];    // [px][par]
    #pragma unroll
    for (int par = 0; par < 2; par++) {
        int c = 2 * cpair + par;
        unsigned G0 = (unsigned)c * HW + (unsigned)p0;
        unsigned F0 = 2u * G0;
        unsigned co0 = F0 >> sh2;           // same for both pixels (p0 even)
        unsigned pq  = F0 & (HW - 1);       // multiple of 4 -> uint4 aligned
        uint4 ow4 = *reinterpret_cast<const uint4*>(
            ob + (size_t)(co0 >> 1) * HW + pq);
        const int parity = co0 & 1;
        const uint32_t* xp = xb + (size_t)cpair * HW;
        #pragma unroll
        for (int px = 0; px < 2; px++) {
            float o0 = unpackh(px ? ow4.z : ow4.x, parity);
            float o1 = unpackh(px ? ow4.w : ow4.y, parity);
            float r  = fminf(fmaxf(o0 + (float)h,         0.0f), (float)(H - 1));
            float cc = fminf(fmaxf(o1 + (float)(w0 + px), 0.0f), (float)(W - 1));
            float r0f = floorf(r), c0f = floorf(cc);
            int r0 = (int)r0f, r1 = (int)ceilf(r);
            int c0 = (int)c0f, c1 = (int)ceilf(cc);
            float vlt = unpackh(xp[(r0 << wsh) + c0], par);
            float vrb = unpackh(xp[(r1 << wsh) + c1], par);
            float vlb = unpackh(xp[(r0 << wsh) + c1], par);
            float vrt = unpackh(xp[(r1 << wsh) + c0], par);
            float fr = r - r0f, fc = cc - c0f;
            float vt = vlt + (vrt - vlt) * fr;
            float vb = vlb + (vrb - vlb) * fr;
            res[px][par] = vt + (vb - vt) * fc;
        }
    }
    *reinterpret_cast<uint2*>(out + (size_t)idx * 2) =
        make_uint2(packh2(res[0][0], res[0][1]), packh2(res[1][0], res[1][1]));
}

// ---------------------------------------------------------------------------
// Weight prepass (ONE launch): all 7 tensors -> half2, linear layout
// [g][ch(16ci)][cb2(NCB)][ks(9)][gid(8)][tig(4)][q(4)]:
//   co = g*(NCB*16) + cb2*16 + gid + (q&1)*8, cipair = tig + (q>>1)*4
//   half2 = (W[ci even], W[ci odd]) at tap ks, ci = ch*16 + cipair*2.
// ---------------------------------------------------------------------------
struct PrepDesc {
    const float* src[7];
    int cin[7];
    int ncb[7];
    int off[8];         // prefix sums in u32 elements
};

__global__ void prep_all_h(PrepDesc d, uint32_t* __restrict__ dst)
{
    int i = blockIdx.x * 256 + threadIdx.x;
    if (i >= d.off[7]) return;
    int s = 0;
    #pragma unroll
    for (int k = 0; k < 6; k++) s += (i >= d.off[k + 1]) ? 1 : 0;
    int j = i - d.off[s];
    const int CIN = d.cin[s];
    const int NCH = CIN >> 4;
    const int NCB = d.ncb[s];

    int q   = j & 3;
    int tig = (j >> 2) & 3;
    int gid = (j >> 4) & 7;
    int ks  = (j >> 7) % 9;
    int rest = j / 1152;
    int cb2 = rest % NCB; rest /= NCB;
    int ch  = rest % NCH;
    int gi  = rest / NCH;

    int co = gi * (NCB * 16) + cb2 * 16 + gid + (q & 1) * 8;
    int cipair = tig + (q >> 1) * 4;
    int ci = ch * 16 + cipair * 2;
    const float* sp = d.src[s] + (((size_t)co * CIN + ci) * 9 + ks);
    dst[i] = packh2(sp[0], sp[9]);
}

// ---------------------------------------------------------------------------
// x prepass: NCHW f32 -> interleaved half2 (vectorized 4 px/thread).
// ---------------------------------------------------------------------------
__global__ void cvt_x4(const float4* __restrict__ src, uint4* __restrict__ dst,
                       int sh2m2, int total4)
{
    int i = blockIdx.x * 256 + threadIdx.x;
    if (i >= total4) return;
    int poff = i & ((1 << sh2m2) - 1);
    int pair = i >> sh2m2;
    float4 a = src[(((size_t)pair * 2)     << sh2m2) + poff];
    float4 c = src[(((size_t)pair * 2 + 1) << sh2m2) + poff];
    dst[i] = make_uint4(packh2(a.x, c.x), packh2(a.y, c.y),
                        packh2(a.z, c.z), packh2(a.w, c.w));
}

// ---------------------------------------------------------------------------
// Global average pool from interleaved half2. One block per channel pair.
// ---------------------------------------------------------------------------
__global__ void avgpool_h(const uint32_t* __restrict__ in,
                          float* __restrict__ out, int HW, int halfC)
{
    const uint32_t* p = in + (size_t)blockIdx.x * HW;
    float lo = 0.0f, hi = 0.0f;
    for (int i = threadIdx.x; i < HW; i += 256) {
        float2 f = __half22float2(*reinterpret_cast<const __half2*>(p + i));
        lo += f.x; hi += f.y;
    }
    __shared__ float smlo[256], smhi[256];
    smlo[threadIdx.x] = lo; smhi[threadIdx.x] = hi;
    __syncthreads();
    for (int st = 128; st > 0; st >>= 1) {
        if (threadIdx.x < st) {
            smlo[threadIdx.x] += smlo[threadIdx.x + st];
            smhi[threadIdx.x] += smhi[threadIdx.x + st];
        }
        __syncthreads();
    }
    if (threadIdx.x == 0) {
        int b = blockIdx.x / halfC, cp = blockIdx.x % halfC;
        out[b * 2 * halfC + 2 * cp]     = smlo[0] / (float)HW;
        out[b * 2 * halfC + 2 * cp + 1] = smhi[0] / (float)HW;
    }
}

// ---------------------------------------------------------------------------
// Launch pipeline (graph-capturable: kernel launches + attribute sets only).
// ---------------------------------------------------------------------------
static inline int conv_smem_bytes(int stride, int th, int ncb, int cin)
{
    int tih  = th * stride + 2;
    int tiwp = (32 * stride + 5 + 3) & ~3;
    int che  = tih * tiwp;
    int chep = ((che + 8 + 31) & ~31) | 8;
    int tile_n = 8 * chep;
    int nch = cin / 16;
    int nb = (nch <= 2) ? 2 : 3;
    return (nch * ncb * 1152 + nb * tile_n) * 4;
}

extern "C" void kernel_launch(void* const* d_in, const int* in_sizes, int n_in,
                              void* d_out, int out_size)
{
    const float* x   = (const float*)d_in[0];
    const float* w1  = (const float*)d_in[1];
    const float* b1  = (const float*)d_in[2];
    const float* ow1 = (const float*)d_in[3];
    const float* w2  = (const float*)d_in[4];
    const float* b2  = (const float*)d_in[5];
    const float* ow2 = (const float*)d_in[6];
    const float* w3  = (const float*)d_in[7];
    const float* b3  = (const float*)d_in[8];
    const float* ow3 = (const float*)d_in[9];
    const float* w4  = (const float*)d_in[10];
    const float* b4  = (const float*)d_in[11];
    float* outp = (float*)d_out;

    float *Af, *Bf, *Cf, *WTf;
    cudaGetSymbolAddress((void**)&Af, g_bufA);
    cudaGetSymbolAddress((void**)&Bf, g_bufB);
    cudaGetSymbolAddress((void**)&Cf, g_bufC);
    cudaGetSymbolAddress((void**)&WTf, g_wt);
    uint32_t* A  = (uint32_t*)Af;
    uint32_t* B  = (uint32_t*)Bf;
    uint32_t* C  = (uint32_t*)Cf;
    uint32_t* WT = (uint32_t*)WTf;

    const int S_C1  = conv_smem_bytes(1, 8, 2, 32);   // conv1: 45568
    const int S_O1  = conv_smem_bytes(1, 8, 4, 32);   // offconv1/3: 64000
    const int S_O2  = conv_smem_bytes(1, 8, 4, 64);   // offconv2: 114432
    const int S_S2  = conv_smem_bytes(2, 4, 2, 32);   // conv2/conv4: 66048
    const int S_S2L = conv_smem_bytes(2, 4, 2, 64);   // conv3: 108288
    cudaFuncSetAttribute(conv3x3_h<1, 32, 1, 8, 2, 3>, cudaFuncAttributeMaxDynamicSharedMemorySize, S_C1);
    cudaFuncSetAttribute(conv3x3_h<1, 32, 0, 8, 4, 2>, cudaFuncAttributeMaxDynamicSharedMemorySize, S_O1);
    cudaFuncSetAttribute(conv3x3_h<1, 64, 0, 8, 4, 2>, cudaFuncAttributeMaxDynamicSharedMemorySize, S_O2);
    cudaFuncSetAttribute(conv3x3_h<2, 32, 1, 4, 1, 3>, cudaFuncAttributeMaxDynamicSharedMemorySize, S_S2);
    cudaFuncSetAttribute(conv3x3_h<2, 64, 1, 4, 1, 2>, cudaFuncAttributeMaxDynamicSharedMemorySize, S_S2L);

    // Prepacked weights (u32 offsets): w1 4608 | ow1 9216 | w2 9216 |
    // ow2 36864 | w3 9216 | ow3 9216 | w4 4608
    uint32_t* w1t  = WT;
    uint32_t* ow1t = WT + 4608;
    uint32_t* w2t  = WT + 13824;
    uint32_t* ow2t = WT + 23040;
    uint32_t* w3t  = WT + 59904;
    uint32_t* ow3t = WT + 69120;
    uint32_t* w4t  = WT + 78336;

    {
        PrepDesc d;
        d.src[0] = w1;  d.cin[0] = 32; d.ncb[0] = 2;
        d.src[1] = ow1; d.cin[1] = 32; d.ncb[1] = 4;
        d.src[2] = w2;  d.cin[2] = 32; d.ncb[2] = 2;
        d.src[3] = ow2; d.cin[3] = 64; d.ncb[3] = 4;
        d.src[4] = w3;  d.cin[4] = 64; d.ncb[4] = 2;
        d.src[5] = ow3; d.cin[5] = 32; d.ncb[5] = 4;
        d.src[6] = w4;  d.cin[6] = 32; d.ncb[6] = 2;
        d.off[0] = 0;     d.off[1] = 4608;  d.off[2] = 13824;
        d.off[3] = 23040; d.off[4] = 59904; d.off[5] = 69120;
        d.off[6] = 78336; d.off[7] = 82944;
        prep_all_h<<<(82944 + 255) / 256, 256>>>(d, WT);
    }
    {
        // x (16,32,256,256) f32 -> interleaved half2 in C
        int total4 = 16 * 16 * 65536 / 4;   // u32 count / 4
        cvt_x4<<<(total4 + 255) / 256, 256>>>((const float4*)x, (uint4*)C, 14, total4);
    }

    // 1) conv1: C(x~) -> A (16,32,256,256), bias+relu  [M=2, OCC=3]
    conv3x3_h<1, 32, 1, 8, 2, 3><<<dim3(8, 32, 16), 256, S_C1>>>(C, w1t, b1, A, 32, 256, 256);

    // 2) offconv1: A -> B (16,64,256,256)  [M=4, 64-cout blocks]
    conv3x3_h<1, 32, 0, 8, 4, 2><<<dim3(8, 32, 16), 256, S_O1>>>(A, ow1t, nullptr, B, 64, 256, 256);

    // 3) deform1: A,B -> C (16,32,256,256) ; 8.39M pixel-pairs
    deform_h2<<<32768, 256>>>(A, B, C, 8, 8, 5, 16 * 16 * 65536 / 2);

    // 4) conv2 stride2: C -> A (16,64,128,128), bias+relu
    conv3x3_h<2, 32, 1, 4, 1, 3><<<dim3(4, 32, 32), 256, S_S2>>>(C, w2t, b2, A, 64, 256, 256);

    // 5) offconv2: A -> B (16,128,128,128)  [M=4, NCH=4, 3-buffer ring]
    conv3x3_h<1, 64, 0, 8, 4, 2><<<dim3(4, 16, 32), 256, S_O2>>>(A, ow2t, nullptr, B, 128, 128, 128);

    // 6) deform2: A,B -> C (16,64,128,128) ; 4.19M pixel-pairs
    deform_h2<<<16384, 256>>>(A, B, C, 7, 7, 6, 16 * 32 * 16384 / 2);

    // 7) conv3 stride2: C -> A (16,32,64,64), bias+relu  [NCH=4 -> OCC=2]
    conv3x3_h<2, 64, 1, 4, 1, 2><<<dim3(2, 16, 16), 256, S_S2L>>>(C, w3t, b3, A, 32, 128, 128);

    // 8) offconv3: A -> B (16,64,64,64)  [M=4]
    conv3x3_h<1, 32, 0, 8, 4, 2><<<dim3(2, 8, 16), 256, S_O1>>>(A, ow3t, nullptr, B, 64, 64, 64);

    // 9) deform3: A,B -> C (16,32,64,64) ; 524288 pixel-pairs
    deform_h2<<<2048, 256>>>(A, B, C, 6, 6, 5, 16 * 16 * 4096 / 2);

    // 10) conv4 stride2: C -> A (16,32,32,32), bias+relu
    conv3x3_h<2, 32, 1, 4, 1, 3><<<dim3(1, 8, 16), 256, S_S2>>>(C, w4t, b4, A, 32, 64, 64);

    // 11) global avg pool: A (interleaved) -> out f32 (16,32,1,1)
    avgpool_h<<<256, 256>>>(A, outp, 1024, 16);
}

// round 17
// speedup vs baseline: 1.0588x; 1.0556x over previous
#include <cuda_runtime.h>
#include <cuda_fp16.h>
#include <cstdint>

// ---------------------------------------------------------------------------
// Scratch buffers (static __device__ globals — no allocation allowed).
// Activations live here as channel-pair-interleaved half2 (viewed as u32).
// ---------------------------------------------------------------------------
__device__ float g_bufA[33554432];
__device__ float g_bufB[67108864];
__device__ float g_bufC[33554432];
__device__ float g_wt[262144];          // prepacked half2 weights (u32 view)

// ---------------------------------------------------------------------------
// Helpers
// ---------------------------------------------------------------------------
__device__ __forceinline__ uint32_t packh2(float lo, float hi)
{
    __half2 h = __floats2half2_rn(lo, hi);   // .x = lo = low 16 bits
    return *reinterpret_cast<uint32_t*>(&h);
}

__device__ __forceinline__ float unpackh(uint32_t u, int parity)
{
    __half2 h = *reinterpret_cast<__half2*>(&u);
    return __half2float(parity ? __high2half(h) : __low2half(h));
}

__device__ __forceinline__ void mma_f16(float* c,
                                        uint32_t a0, uint32_t a1,
                                        uint32_t a2, uint32_t a3,
                                        uint32_t b0, uint32_t b1)
{
    asm volatile(
        "mma.sync.aligned.m16n8k16.row.col.f32.f16.f16.f32 "
        "{%0,%1,%2,%3}, {%4,%5,%6,%7}, {%8,%9}, {%0,%1,%2,%3};\n"
        : "+f"(c[0]), "+f"(c[1]), "+f"(c[2]), "+f"(c[3])
        : "r"(a0), "r"(a1), "r"(a2), "r"(a3), "r"(b0), "r"(b1));
}

__device__ __forceinline__ uint32_t smem_u32(const void* p)
{
    return (uint32_t)__cvta_generic_to_shared(p);
}

// 16B cp.async; src-size 0 -> 16 zero bytes written (halo padding).
__device__ __forceinline__ void cp16z(uint32_t dst, const void* src, bool ok)
{
    int sz = ok ? 16 : 0;
    asm volatile("cp.async.ca.shared.global [%0], [%1], 16, %2;"
                 :: "r"(dst), "l"(src), "r"(sz));
}

// ---------------------------------------------------------------------------
// Implicit-GEMM 3x3 conv (pad=1), fp16 mma.sync.m16n8k16, f32 accumulate.
// Activations channel-pair-interleaved half2 (one u32 per pixel per cpair).
//
// Unified tiling <STRIDE, CIN, BR, MM, ROWS, NWARPS, OCC>:
//   block = NWARPS*32 threads; output tile = MM*16 couts x (TH h x 32 w),
//   TH = NWARPS*ROWS. Warp nq covers rows nq + rr*NWARPS (rr<ROWS) and all
//   MM co-tiles; B fragments loaded once per (ks,rr,t) and reused across MM,
//   A fragments once per (ks,m) reused across ROWS*4 n-tiles:
//   wavefronts/MMA = 4/(4*ROWS) + 2/MM  (1.5 at MM=4 or MM=2&ROWS=2).
// Pipeline: ALL weights staged into smem ONCE (chunk-invariant); chunk loop
// stages tiles only, depth-1 ahead, NB-buffer ring (NB=3 when NCH=4), ONE
// __syncthreads per chunk.
// K order: k = r*16 + cipair*2 + parity (r = dy*3+dx); per-ks tap offsets
// are compile-time immediates. Weight smem [cb2(MM)][ks][gid][tig][q]: A
// fragment = ONE LDS.128, staging = affine 16B copy.
// CHEP ≡ 8 (mod 32) -> stride-1 B loads conflict-free.
// ---------------------------------------------------------------------------
template<int STRIDE, int CIN, int BR, int MM, int ROWS, int NWARPS, int OCC>
__global__ __launch_bounds__(NWARPS * 32, OCC)
void conv3x3_h(const uint32_t* __restrict__ in, const uint32_t* __restrict__ w,
               const float* __restrict__ bias, uint32_t* __restrict__ out,
               int Cout, int Hin, int Win)
{
    constexpr int NTHR = NWARPS * 32;
    constexpr int TH   = NWARPS * ROWS;
    constexpr int TIH  = TH * STRIDE + 2;
    constexpr int TIWP = (32 * STRIDE + 5 + 3) & ~3;    // 40 / 72 (pixels=u32)
    constexpr int RU   = TIWP / 4;                      // 16B units per row
    constexpr int PL   = TIH * RU;                      // units per cp plane
    constexpr int CHE  = TIH * TIWP;
    constexpr int CHEP = ((CHE + 8 + 31) & ~31) | 8;    // ≡8 mod 32
    constexpr int TILE_N = 8 * CHEP;                    // u32 per tile buffer
    constexpr int NCH  = CIN / 16;                      // 16 ci per chunk
    constexpr int NB   = (NCH <= 2) ? 2 : 3;            // tile ring depth
    constexpr int WN   = MM * 1152;                     // u32 per weight chunk
    constexpr int WALL = NCH * WN;                      // u32, all weights
    constexpr int TU   = 8 * PL;
    constexpr int TITER = (TU + NTHR - 1) / NTHR;
    constexpr bool HOIST = (STRIDE == 1);

    extern __shared__ __align__(16) uint32_t smem[];    // [w_all | tiles NB]

    const int Hout = Hin / STRIDE, Wout = Win / STRIDE;
    const int tid = threadIdx.x;
    const int groups = Cout / (MM * 16);
    const int g  = blockIdx.z % groups;
    const int b  = blockIdx.z / groups;
    const int bx = blockIdx.x, by = blockIdx.y;

    const int y0 = by * TH * STRIDE - 1;
    const int x0 = bx * 32 * STRIDE - 4;    // 16B-aligned halo (logical -1 = col 3)
    const size_t HW = (size_t)Hin * Win;    // u32 per channel pair
    const uint32_t* ibase = in + (size_t)b * (CIN / 2) * HW;
    const uint32_t* wbase = w + (size_t)g * WALL;

    const uint32_t wbuf_s = smem_u32(smem);
    const uint32_t tile_s = smem_u32(smem + WALL);

    // --- hoisted tile-staging descriptors (stride-1 only) ---
    int      h_soff[TITER];
    uint32_t h_doff[TITER];
    bool     h_ok[TITER];
    if (HOIST) {
        #pragma unroll
        for (int it = 0; it < TITER; it++) {
            int u = tid + it * NTHR;
            int uc = (u < TU) ? u : 0;
            int cp8 = uc / PL;
            int rem = uc - cp8 * PL;
            int r = rem / RU, uu = rem - r * RU;
            int gy = y0 + r, gx = x0 + 4 * uu;
            h_ok[it]   = (gy >= 0) && (gy < Hin) && (gx >= 0) && (gx < Win);
            h_soff[it] = cp8 * (int)HW + gy * Win + gx;
            h_doff[it] = 4u * (uint32_t)(cp8 * CHEP + r * TIWP + 4 * uu);
        }
    }

    auto load_tile = [&](int ch, int bi) {
        const uint32_t* isrc = ibase + (size_t)(ch * 8) * HW;
        uint32_t td = tile_s + (uint32_t)bi * 4u * TILE_N;
        if (HOIST) {
            #pragma unroll
            for (int it = 0; it < TITER; it++)
                if (tid + it * NTHR < TU)
                    cp16z(td + h_doff[it], isrc + h_soff[it], h_ok[it]);
        } else {
            #pragma unroll 4
            for (int u = tid; u < TU; u += NTHR) {
                int cp8 = u / PL;
                int rem = u - cp8 * PL;
                int r = rem / RU, uu = rem - r * RU;
                int gy = y0 + r, gx = x0 + 4 * uu;
                bool ok = (gy >= 0) && (gy < Hin) && (gx >= 0) && (gx < Win);
                cp16z(td + 4u * (uint32_t)(cp8 * CHEP + r * TIWP + 4 * uu),
                      isrc + (size_t)cp8 * HW + (size_t)gy * Win + gx, ok);
            }
        }
    };

    const int lane = tid & 31, wid = tid >> 5;
    const int tig = lane & 3, gid = lane >> 2;
    const int nq = wid;

    float acc[MM][ROWS * 4][4];
    #pragma unroll
    for (int m = 0; m < MM; m++) {
        float bv0 = 0.0f, bv1 = 0.0f;
        if (BR) {
            bv0 = bias[g * (MM * 16) + m * 16 + gid];
            bv1 = bias[g * (MM * 16) + m * 16 + gid + 8];
        }
        #pragma unroll
        for (int t = 0; t < ROWS * 4; t++) {
            acc[m][t][0] = bv0; acc[m][t][1] = bv0;
            acc[m][t][2] = bv1; acc[m][t][3] = bv1;
        }
    }

    // Prologue: ALL weights (affine 16B copy) + tile 0, one commit group.
    #pragma unroll 4
    for (int u = tid; u < WALL / 4; u += NTHR)
        cp16z(wbuf_s + 16u * (uint32_t)u, wbase + 4 * u, true);
    load_tile(0, 0);
    asm volatile("cp.async.commit_group;");

    #pragma unroll
    for (int ch = 0; ch < NCH; ch++) {
        if (ch + 1 < NCH) {
            load_tile(ch + 1, (ch + 1) % NB);
            asm volatile("cp.async.commit_group;");
            asm volatile("cp.async.wait_group 1;");
        } else {
            asm volatile("cp.async.wait_group 0;");
        }
        __syncthreads();    // ONE barrier per chunk

        const uint32_t* st = smem + WALL + (ch % NB) * TILE_N;
        const uint32_t* sw = smem + ch * WN;
        const uint32_t* bp1 = st + tig * CHEP + nq * STRIDE * TIWP + gid * STRIDE + 3;
        const uint32_t* bp2 = bp1 + 4 * CHEP;
        const uint32_t* apb = sw + 4 * lane;

        #pragma unroll
        for (int ks = 0; ks < 9; ks++) {
            const int KO = (ks / 3) * TIWP + (ks % 3);   // compile-time per ks
            uint4 va[MM];
            #pragma unroll
            for (int m = 0; m < MM; m++)
                va[m] = *reinterpret_cast<const uint4*>(apb + m * 1152 + ks * 128);
            #pragma unroll
            for (int rr = 0; rr < ROWS; rr++) {
                const int RO = KO + rr * (NWARPS * STRIDE * TIWP);
                #pragma unroll
                for (int t = 0; t < 4; t++) {
                    uint32_t b0 = bp1[RO + t * 8 * STRIDE];
                    uint32_t b1 = bp2[RO + t * 8 * STRIDE];
                    #pragma unroll
                    for (int m = 0; m < MM; m++)
                        mma_f16(acc[m][rr * 4 + t],
                                va[m].x, va[m].y, va[m].z, va[m].w, b0, b1);
                }
            }
        }
    }

    // Epilogue: pair up (even, odd) co via shfl_xor(4), store half2 (u32x2).
    const size_t HWo = (size_t)Hout * Wout;
    #pragma unroll
    for (int m = 0; m < MM; m++) {
        const int cbg = g * (MM * 16) + m * 16;
        #pragma unroll
        for (int rr = 0; rr < ROWS; rr++) {
            const int hrow = by * TH + nq + rr * NWARPS;
            #pragma unroll
            for (int t = 0; t < 4; t++) {
                const int t2 = rr * 4 + t;
                float v0 = acc[m][t2][0], v1 = acc[m][t2][1];
                float v2 = acc[m][t2][2], v3 = acc[m][t2][3];
                if (BR) {
                    v0 = fmaxf(v0, 0.0f); v1 = fmaxf(v1, 0.0f);
                    v2 = fmaxf(v2, 0.0f); v3 = fmaxf(v3, 0.0f);
                }
                float p0 = __shfl_xor_sync(0xffffffffu, v0, 4);
                float p1 = __shfl_xor_sync(0xffffffffu, v1, 4);
                float p2 = __shfl_xor_sync(0xffffffffu, v2, 4);
                float p3 = __shfl_xor_sync(0xffffffffu, v3, 4);
                const int wg = bx * 32 + t * 8 + 2 * tig;
                uint2 st2;
                int copair;
                if ((gid & 1) == 0) {
                    st2.x = packh2(v0, p0);
                    st2.y = packh2(v1, p1);
                    copair = (cbg + gid) >> 1;
                } else {
                    st2.x = packh2(p2, v2);
                    st2.y = packh2(p3, v3);
                    copair = (cbg + gid + 7) >> 1;
                }
                *reinterpret_cast<uint2*>(
                    out + ((size_t)b * (Cout / 2) + copair) * HWo
                        + (size_t)hrow * Wout + wg) = st2;
            }
        }
    }
}

// ---------------------------------------------------------------------------
// ConvOffset2D bilinear sampling on interleaved-half2 buffers, TWO adjacent
// pixels per thread (one 16B offset load, one uint2 store).
// ---------------------------------------------------------------------------
__global__ void deform_h2(const uint32_t* __restrict__ x,
                          const uint32_t* __restrict__ off,
                          uint32_t* __restrict__ out,
                          int wsh, int hsh, int csh, int total_out2)
{
    int idx = blockIdx.x * 256 + threadIdx.x;
    if (idx >= total_out2) return;
    const int W = 1 << wsh, H = 1 << hsh;
    const int sh2 = wsh + hsh;
    const unsigned HW = 1u << sh2;
    const int C = 1 << csh;

    int pp2 = idx & ((HW >> 1) - 1);
    int p0 = pp2 * 2;
    int cpair = (idx >> (sh2 - 1)) & ((1 << (csh - 1)) - 1);
    int b = idx >> (sh2 - 1 + csh - 1);
    int h = p0 >> wsh;
    int w0 = p0 & (W - 1);

    const uint32_t* xb = x + (size_t)b * (C / 2) * HW;
    const uint32_t* ob = off + (size_t)b * C * HW;

    float res[2][2];    // [px][par]
    #pragma unroll
    for (int par = 0; par < 2; par++) {
        int c = 2 * cpair + par;
        unsigned G0 = (unsigned)c * HW + (unsigned)p0;
        unsigned F0 = 2u * G0;
        unsigned co0 = F0 >> sh2;
        unsigned pq  = F0 & (HW - 1);
        uint4 ow4 = *reinterpret_cast<const uint4*>(
            ob + (size_t)(co0 >> 1) * HW + pq);
        const int parity = co0 & 1;
        const uint32_t* xp = xb + (size_t)cpair * HW;
        #pragma unroll
        for (int px = 0; px < 2; px++) {
            float o0 = unpackh(px ? ow4.z : ow4.x, parity);
            float o1 = unpackh(px ? ow4.w : ow4.y, parity);
            float r  = fminf(fmaxf(o0 + (float)h,         0.0f), (float)(H - 1));
            float cc = fminf(fmaxf(o1 + (float)(w0 + px), 0.0f), (float)(W - 1));
            float r0f = floorf(r), c0f = floorf(cc);
            int r0 = (int)r0f, r1 = (int)ceilf(r);
            int c0 = (int)c0f, c1 = (int)ceilf(cc);
            float vlt = unpackh(xp[(r0 << wsh) + c0], par);
            float vrb = unpackh(xp[(r1 << wsh) + c1], par);
            float vlb = unpackh(xp[(r0 << wsh) + c1], par);
            float vrt = unpackh(xp[(r1 << wsh) + c0], par);
            float fr = r - r0f, fc = cc - c0f;
            float vt = vlt + (vrt - vlt) * fr;
            float vb = vlb + (vrb - vlb) * fr;
            res[px][par] = vt + (vb - vt) * fc;
        }
    }
    *reinterpret_cast<uint2*>(out + (size_t)idx * 2) =
        make_uint2(packh2(res[0][0], res[0][1]), packh2(res[1][0], res[1][1]));
}

// ---------------------------------------------------------------------------
// Weight prepass (ONE launch): all 7 tensors -> half2, linear layout
// [g][ch(16ci)][cb2(NCB)][ks(9)][gid(8)][tig(4)][q(4)]:
//   co = g*(NCB*16) + cb2*16 + gid + (q&1)*8, cipair = tig + (q>>1)*4
//   half2 = (W[ci even], W[ci odd]) at tap ks, ci = ch*16 + cipair*2.
// ---------------------------------------------------------------------------
struct PrepDesc {
    const float* src[7];
    int cin[7];
    int ncb[7];
    int off[8];         // prefix sums in u32 elements
};

__global__ void prep_all_h(PrepDesc d, uint32_t* __restrict__ dst)
{
    int i = blockIdx.x * 256 + threadIdx.x;
    if (i >= d.off[7]) return;
    int s = 0;
    #pragma unroll
    for (int k = 0; k < 6; k++) s += (i >= d.off[k + 1]) ? 1 : 0;
    int j = i - d.off[s];
    const int CIN = d.cin[s];
    const int NCH = CIN >> 4;
    const int NCB = d.ncb[s];

    int q   = j & 3;
    int tig = (j >> 2) & 3;
    int gid = (j >> 4) & 7;
    int ks  = (j >> 7) % 9;
    int rest = j / 1152;
    int cb2 = rest % NCB; rest /= NCB;
    int ch  = rest % NCH;
    int gi  = rest / NCH;

    int co = gi * (NCB * 16) + cb2 * 16 + gid + (q & 1) * 8;
    int cipair = tig + (q >> 1) * 4;
    int ci = ch * 16 + cipair * 2;
    const float* sp = d.src[s] + (((size_t)co * CIN + ci) * 9 + ks);
    dst[i] = packh2(sp[0], sp[9]);
}

// ---------------------------------------------------------------------------
// x prepass: NCHW f32 -> interleaved half2 (vectorized 4 px/thread).
// ---------------------------------------------------------------------------
__global__ void cvt_x4(const float4* __restrict__ src, uint4* __restrict__ dst,
                       int sh2m2, int total4)
{
    int i = blockIdx.x * 256 + threadIdx.x;
    if (i >= total4) return;
    int poff = i & ((1 << sh2m2) - 1);
    int pair = i >> sh2m2;
    float4 a = src[(((size_t)pair * 2)     << sh2m2) + poff];
    float4 c = src[(((size_t)pair * 2 + 1) << sh2m2) + poff];
    dst[i] = make_uint4(packh2(a.x, c.x), packh2(a.y, c.y),
                        packh2(a.z, c.z), packh2(a.w, c.w));
}

// ---------------------------------------------------------------------------
// Global average pool from interleaved half2. One block per channel pair.
// ---------------------------------------------------------------------------
__global__ void avgpool_h(const uint32_t* __restrict__ in,
                          float* __restrict__ out, int HW, int halfC)
{
    const uint32_t* p = in + (size_t)blockIdx.x * HW;
    float lo = 0.0f, hi = 0.0f;
    for (int i = threadIdx.x; i < HW; i += 256) {
        float2 f = __half22float2(*reinterpret_cast<const __half2*>(p + i));
        lo += f.x; hi += f.y;
    }
    __shared__ float smlo[256], smhi[256];
    smlo[threadIdx.x] = lo; smhi[threadIdx.x] = hi;
    __syncthreads();
    for (int st = 128; st > 0; st >>= 1) {
        if (threadIdx.x < st) {
            smlo[threadIdx.x] += smlo[threadIdx.x + st];
            smhi[threadIdx.x] += smhi[threadIdx.x + st];
        }
        __syncthreads();
    }
    if (threadIdx.x == 0) {
        int b = blockIdx.x / halfC, cp = blockIdx.x % halfC;
        out[b * 2 * halfC + 2 * cp]     = smlo[0] / (float)HW;
        out[b * 2 * halfC + 2 * cp + 1] = smhi[0] / (float)HW;
    }
}

// ---------------------------------------------------------------------------
// Launch pipeline (graph-capturable: kernel launches + attribute sets only).
// ---------------------------------------------------------------------------
static inline int conv_smem_bytes(int stride, int mm, int rows, int nwarps, int cin)
{
    int th   = nwarps * rows;
    int tih  = th * stride + 2;
    int tiwp = (32 * stride + 5 + 3) & ~3;
    int che  = tih * tiwp;
    int chep = ((che + 8 + 31) & ~31) | 8;
    int tile_n = 8 * chep;
    int nch = cin / 16;
    int nb = (nch <= 2) ? 2 : 3;
    return (nch * mm * 1152 + nb * tile_n) * 4;
}

extern "C" void kernel_launch(void* const* d_in, const int* in_sizes, int n_in,
                              void* d_out, int out_size)
{
    const float* x   = (const float*)d_in[0];
    const float* w1  = (const float*)d_in[1];
    const float* b1  = (const float*)d_in[2];
    const float* ow1 = (const float*)d_in[3];
    const float* w2  = (const float*)d_in[4];
    const float* b2  = (const float*)d_in[5];
    const float* ow2 = (const float*)d_in[6];
    const float* w3  = (const float*)d_in[7];
    const float* b3  = (const float*)d_in[8];
    const float* ow3 = (const float*)d_in[9];
    const float* w4  = (const float*)d_in[10];
    const float* b4  = (const float*)d_in[11];
    float* outp = (float*)d_out;

    float *Af, *Bf, *Cf, *WTf;
    cudaGetSymbolAddress((void**)&Af, g_bufA);
    cudaGetSymbolAddress((void**)&Bf, g_bufB);
    cudaGetSymbolAddress((void**)&Cf, g_bufC);
    cudaGetSymbolAddress((void**)&WTf, g_wt);
    uint32_t* A  = (uint32_t*)Af;
    uint32_t* B  = (uint32_t*)Bf;
    uint32_t* C  = (uint32_t*)Cf;
    uint32_t* WT = (uint32_t*)WTf;

    // conv1:    <1,32,1, M=2, ROWS=2, 8w, OCC=2>  wf/MMA 1.5   smem 66048
    // offconv1/3:<1,32,0, M=4, ROWS=1, 8w, OCC=2> wf/MMA 1.5   smem 64000
    // offconv2: <1,64,0, M=4, ROWS=1, 8w, OCC=2>  wf/MMA 1.5   smem 114432
    // conv2:    <2,32,1, M=4, ROWS=1, 4w, OCC=2>  wf/MMA 1.5   smem 84480
    // conv3:    <2,64,1, M=2, ROWS=1, 4w, OCC=2>  wf/MMA 2.0   smem 108288
    // conv4:    <2,32,1, M=2, ROWS=1, 4w, OCC=3>  wf/MMA 2.0   smem 66048
    const int S_C1 = conv_smem_bytes(1, 2, 2, 8, 32);
    const int S_O1 = conv_smem_bytes(1, 4, 1, 8, 32);
    const int S_O2 = conv_smem_bytes(1, 4, 1, 8, 64);
    const int S_C2 = conv_smem_bytes(2, 4, 1, 4, 32);
    const int S_C3 = conv_smem_bytes(2, 2, 1, 4, 64);
    const int S_C4 = conv_smem_bytes(2, 2, 1, 4, 32);
    cudaFuncSetAttribute(conv3x3_h<1, 32, 1, 2, 2, 8, 2>, cudaFuncAttributeMaxDynamicSharedMemorySize, S_C1);
    cudaFuncSetAttribute(conv3x3_h<1, 32, 0, 4, 1, 8, 2>, cudaFuncAttributeMaxDynamicSharedMemorySize, S_O1);
    cudaFuncSetAttribute(conv3x3_h<1, 64, 0, 4, 1, 8, 2>, cudaFuncAttributeMaxDynamicSharedMemorySize, S_O2);
    cudaFuncSetAttribute(conv3x3_h<2, 32, 1, 4, 1, 4, 2>, cudaFuncAttributeMaxDynamicSharedMemorySize, S_C2);
    cudaFuncSetAttribute(conv3x3_h<2, 64, 1, 2, 1, 4, 2>, cudaFuncAttributeMaxDynamicSharedMemorySize, S_C3);
    cudaFuncSetAttribute(conv3x3_h<2, 32, 1, 2, 1, 4, 3>, cudaFuncAttributeMaxDynamicSharedMemorySize, S_C4);

    // Prepacked weights (u32 offsets): w1 4608 | ow1 9216 | w2 9216 |
    // ow2 36864 | w3 9216 | ow3 9216 | w4 4608
    uint32_t* w1t  = WT;
    uint32_t* ow1t = WT + 4608;
    uint32_t* w2t  = WT + 13824;
    uint32_t* ow2t = WT + 23040;
    uint32_t* w3t  = WT + 59904;
    uint32_t* ow3t = WT + 69120;
    uint32_t* w4t  = WT + 78336;

    {
        PrepDesc d;
        d.src[0] = w1;  d.cin[0] = 32; d.ncb[0] = 2;   // conv1   M=2
        d.src[1] = ow1; d.cin[1] = 32; d.ncb[1] = 4;   // offconv1 M=4
        d.src[2] = w2;  d.cin[2] = 32; d.ncb[2] = 4;   // conv2   M=4 (NEW)
        d.src[3] = ow2; d.cin[3] = 64; d.ncb[3] = 4;   // offconv2 M=4
        d.src[4] = w3;  d.cin[4] = 64; d.ncb[4] = 2;   // conv3   M=2
        d.src[5] = ow3; d.cin[5] = 32; d.ncb[5] = 4;   // offconv3 M=4
        d.src[6] = w4;  d.cin[6] = 32; d.ncb[6] = 2;   // conv4   M=2
        d.off[0] = 0;     d.off[1] = 4608;  d.off[2] = 13824;
        d.off[3] = 23040; d.off[4] = 59904; d.off[5] = 69120;
        d.off[6] = 78336; d.off[7] = 82944;
        prep_all_h<<<(82944 + 255) / 256, 256>>>(d, WT);
    }
    {
        // x (16,32,256,256) f32 -> interleaved half2 in C
        int total4 = 16 * 16 * 65536 / 4;   // u32 count / 4
        cvt_x4<<<(total4 + 255) / 256, 256>>>((const float4*)x, (uint4*)C, 14, total4);
    }

    // 1) conv1: C(x~) -> A (16,32,256,256), bias+relu  [TH=16, M=2, ROWS=2]
    conv3x3_h<1, 32, 1, 2, 2, 8, 2><<<dim3(8, 16, 16), 256, S_C1>>>(C, w1t, b1, A, 32, 256, 256);

    // 2) offconv1: A -> B (16,64,256,256)  [M=4]
    conv3x3_h<1, 32, 0, 4, 1, 8, 2><<<dim3(8, 32, 16), 256, S_O1>>>(A, ow1t, nullptr, B, 64, 256, 256);

    // 3) deform1: A,B -> C (16,32,256,256)
    deform_h2<<<32768, 256>>>(A, B, C, 8, 8, 5, 16 * 16 * 65536 / 2);

    // 4) conv2 stride2: C -> A (16,64,128,128), bias+relu  [128thr, M=4]
    conv3x3_h<2, 32, 1, 4, 1, 4, 2><<<dim3(4, 32, 16), 128, S_C2>>>(C, w2t, b2, A, 64, 256, 256);

    // 5) offconv2: A -> B (16,128,128,128)  [M=4, NCH=4, 3-buffer ring]
    conv3x3_h<1, 64, 0, 4, 1, 8, 2><<<dim3(4, 16, 32), 256, S_O2>>>(A, ow2t, nullptr, B, 128, 128, 128);

    // 6) deform2: A,B -> C (16,64,128,128)
    deform_h2<<<16384, 256>>>(A, B, C, 7, 7, 6, 16 * 32 * 16384 / 2);

    // 7) conv3 stride2: C -> A (16,32,64,64), bias+relu  [128thr, M=2]
    conv3x3_h<2, 64, 1, 2, 1, 4, 2><<<dim3(2, 16, 16), 128, S_C3>>>(C, w3t, b3, A, 32, 128, 128);

    // 8) offconv3: A -> B (16,64,64,64)  [M=4]
    conv3x3_h<1, 32, 0, 4, 1, 8, 2><<<dim3(2, 8, 16), 256, S_O1>>>(A, ow3t, nullptr, B, 64, 64, 64);

    // 9) deform3: A,B -> C (16,32,64,64)
    deform_h2<<<2048, 256>>>(A, B, C, 6, 6, 5, 16 * 16 * 4096 / 2);

    // 10) conv4 stride2: C -> A (16,32,32,32), bias+relu  [128thr, M=2]
    conv3x3_h<2, 32, 1, 2, 1, 4, 3><<<dim3(1, 8, 16), 128, S_C4>>>(C, w4t, b4, A, 32, 64, 64);

    // 11) global avg pool: A (interleaved) -> out f32 (16,32,1,1)
    avgpool_h<<<256, 256>>>(A, outp, 1024, 16);
}